// round 15
// baseline (speedup 1.0000x reference)
#include <cuda_runtime.h>
#include <cuda_bf16.h>
#include <math.h>
#include <stddef.h>
#include <stdint.h>

#define BB 8
#define LL 2048
#define NNV 512
#define HHV 16
#define CCV 16
#define DDV 64
#define TKV 45
#define BLV (BB*LL)
#define KCH 17                 // 544/32 chunks (512 data + 16 fold + 16 pad)
#define KI (KCH*64)            // 1088 interleaved elems per row (hi|lo per 32-chunk)
#define NTI ((LL/32)*64)       // 4096 interleaved elems per row for sim operand
#define SIMZ 16

__device__ __forceinline__ void bfsplit(float v, __nv_bfloat16& h, __nv_bfloat16& l) {
    h = __float2bfloat16(v);
    l = __float2bfloat16(v - __bfloat162float(h));
}
__device__ __forceinline__ void mma16816(float& c0, float& c1, float& c2, float& c3,
                                         uint32_t a0, uint32_t a1, uint32_t a2, uint32_t a3,
                                         uint32_t b0, uint32_t b1) {
    asm volatile(
        "mma.sync.aligned.m16n8k16.row.col.f32.bf16.bf16.f32 "
        "{%0,%1,%2,%3}, {%4,%5,%6,%7}, {%8,%9}, {%0,%1,%2,%3};"
        : "+f"(c0), "+f"(c1), "+f"(c2), "+f"(c3)
        : "r"(a0), "r"(a1), "r"(a2), "r"(a3), "r"(b0), "r"(b1));
}
__device__ __forceinline__ uint32_t smem_u32(const void* p) {
    uint32_t a;
    asm("{ .reg .u64 t; cvta.to.shared.u64 t, %1; cvt.u32.u64 %0, t; }" : "=r"(a) : "l"(p));
    return a;
}
__device__ __forceinline__ void cp16(uint32_t dst, const void* src) {
    asm volatile("cp.async.cg.shared.global [%0], [%1], 16;" :: "r"(dst), "l"(src));
}
__device__ __forceinline__ void ldsm_x4(uint32_t* r, uint32_t addr) {
    asm volatile("ldmatrix.sync.aligned.m8n8.x4.shared.b16 {%0,%1,%2,%3}, [%4];"
                 : "=r"(r[0]), "=r"(r[1]), "=r"(r[2]), "=r"(r[3]) : "r"(addr));
}
__device__ __forceinline__ void ldsm_x2(uint32_t* r, uint32_t addr) {
    asm volatile("ldmatrix.sync.aligned.m8n8.x2.shared.b16 {%0,%1}, [%2];"
                 : "=r"(r[0]), "=r"(r[1]) : "r"(addr));
}

// ===================== scratch (device globals) =====================
__device__ float g_simpart[SIMZ*NNV*NNV];
__device__ float g_sim[NNV*NNV];
__device__ int   g_topk[NNV*TKV];
__device__ float g_attn[BB*NNV*TKV];
__device__ float g_Q[BB*NNV*HHV];
__device__ float g_K[BB*NNV*HHV];
__device__ float g_imp[BB*NNV];
__device__ float g_summary[BB*NNV];
__device__ float g_ps[BB*16*NNV];
__device__ float g_pq[BB*16*NNV];
__device__ float g_cw[NNV*CCV];
__device__ float g_cwT[CCV*NNV];
__device__ float g_M1[CCV*DDV];
__device__ float g_bb[DDV];
__device__ float g_w2[DDV];
__device__ float g_b2s;
__device__ float g_ct[BB*CCV*DDV];
__device__ float g_ctp[BB*CCV*DDV];
__device__ float g_xcs[(size_t)BLV*CCV];
__device__ float g_c2v[(size_t)BLV*NNV];
__device__ float g_h[(size_t)BLV*NNV];
__device__ __align__(16) __nv_bfloat16 g_nT[(size_t)NNV*NTI];
__device__ __align__(16) __nv_bfloat16 g_A1[(size_t)BLV*KI];
__device__ __align__(16) __nv_bfloat16 g_A2[(size_t)BLV*KI];
__device__ __align__(16) __nv_bfloat16 g_B1[(size_t)NNV*KI];
__device__ __align__(16) __nv_bfloat16 g_B2[(size_t)NNV*KI];

// ========== 1. column stats -> normedT interleaved hi|lo (smem transpose) ====
__global__ void k_colstats(const float* __restrict__ x) {
    __shared__ float tile[64][65];
    int l0 = blockIdx.x*64, n0 = blockIdx.y*64;
    int tid = threadIdx.x;
#pragma unroll
    for (int it = 0; it < 16; it++) {
        int id = it*256 + tid;
        int dl = id >> 6, dn = id & 63;
        size_t off = (size_t)(l0+dl)*NNV + n0 + dn;
        float v[BB];
#pragma unroll
        for (int b = 0; b < BB; b++) v[b] = x[(size_t)b*LL*NNV + off];
        float s = 0.f;
#pragma unroll
        for (int b = 0; b < BB; b++) s += v[b];
        float mean = s * (1.0f/BB);
        float q = 0.f;
#pragma unroll
        for (int b = 0; b < BB; b++) { float d = v[b]-mean; q += d*d; }
        float stdv = sqrtf(q * (1.0f/(BB-1))) + 1e-5f;
        tile[dn][dl] = mean / stdv;
    }
    __syncthreads();
#pragma unroll
    for (int it = 0; it < 16; it++) {
        int id = it*256 + tid;
        int dn = id >> 6, dl = id & 63;
        float v = tile[dn][dl];
        __nv_bfloat16 h, lo;
        bfsplit(v, h, lo);
        int l = l0 + dl;
        size_t o = (size_t)(n0+dn)*NTI + (size_t)(l>>5)*64 + (l&31);
        g_nT[o] = h;
        g_nT[o+32] = lo;
    }
}

// ========= sim GEMM: 3-stage pipelined 3-pass bf16 HMMA (SW128, R8) ==========
#define STAGEB 32768

__global__ void __launch_bounds__(256, 2) k_gsim(
    const __nv_bfloat16* __restrict__ A, int lda, int kz32, int nStages,
    float* __restrict__ outF)
{
    extern __shared__ __align__(16) __nv_bfloat16 sm[];
    const uint32_t smb = smem_u32(sm);
    int tid = threadIdx.x;
    int wid = tid >> 5, lane = tid & 31;
    int gr = lane >> 2, tc = lane & 3;
    int warpM = wid >> 2, warpN = wid & 3;
    int row0 = blockIdx.y * 128, col0 = blockIdx.x * 128;
    int kStart32 = blockIdx.z * kz32;

    float acc[4][4][4];
#pragma unroll
    for (int mt = 0; mt < 4; mt++)
#pragma unroll
        for (int nt = 0; nt < 4; nt++)
#pragma unroll
            for (int i = 0; i < 4; i++) acc[mt][nt][i] = 0.f;

    int aR = warpM*64 + (lane & 15);
    int aKey = aR & 7;
    uint32_t aRow = (uint32_t)aR * 128;
    int aSel = lane >> 4;
    int bR = warpN*32 + (lane & 7);
    int bKey = bR & 7;
    uint32_t bRow = (uint32_t)bR * 128;
    int bSel = (lane >> 3) & 1;

#define LOAD_STAGE(S) do { \
    uint32_t _sb = smb + (uint32_t)((S) % 3) * STAGEB; \
    int _k0 = (kStart32 + (S)) * 64; \
    _Pragma("unroll") \
    for (int _j = 0; _j < 4; _j++) { \
        int _idx = tid + _j*256; \
        int _r = _idx >> 3, _c = _idx & 7; \
        uint32_t _sw = (uint32_t)(_r*128) + (uint32_t)((_c ^ (_r & 7)) << 4); \
        cp16(_sb + _sw,         A + (size_t)(row0+_r)*lda + _k0 + _c*8); \
        cp16(_sb + 16384 + _sw, A + (size_t)(col0+_r)*lda + _k0 + _c*8); \
    } } while (0)

    LOAD_STAGE(0);
    asm volatile("cp.async.commit_group;");
    if (nStages > 1) LOAD_STAGE(1);
    asm volatile("cp.async.commit_group;");

    for (int s = 0; s < nStages; s++) {
        if (s + 2 < nStages) LOAD_STAGE(s + 2);
        asm volatile("cp.async.commit_group;");
        asm volatile("cp.async.wait_group 2;");
        __syncthreads();
        uint32_t bufA = smb + (uint32_t)(s % 3) * STAGEB;
        uint32_t bufB = bufA + 16384;
#pragma unroll
        for (int kk = 0; kk < 2; kk++) {
            int cAh = kk*2 + aSel, cAl = cAh + 4;
            int cBh = kk*2 + bSel, cBl = cBh + 4;
            uint32_t aOffH = (uint32_t)((cAh ^ aKey) << 4);
            uint32_t aOffL = (uint32_t)((cAl ^ aKey) << 4);
            uint32_t bOffH = (uint32_t)((cBh ^ bKey) << 4);
            uint32_t bOffL = (uint32_t)((cBl ^ bKey) << 4);
            uint32_t aH[4][4], aL[4][4];
#pragma unroll
            for (int mt = 0; mt < 4; mt++) {
                uint32_t base = bufA + aRow + mt*2048;
                ldsm_x4(aH[mt], base + aOffH);
                ldsm_x4(aL[mt], base + aOffL);
            }
            uint32_t bH[4][2], bL[4][2];
#pragma unroll
            for (int nt = 0; nt < 4; nt++) {
                uint32_t base = bufB + bRow + nt*1024;
                ldsm_x2(bH[nt], base + bOffH);
                ldsm_x2(bL[nt], base + bOffL);
            }
#pragma unroll
            for (int mt = 0; mt < 4; mt++)
#pragma unroll
                for (int nt = 0; nt < 4; nt++) {
                    float* c = acc[mt][nt];
                    mma16816(c[0],c[1],c[2],c[3], aH[mt][0],aH[mt][1],aH[mt][2],aH[mt][3], bH[nt][0],bH[nt][1]);
                    mma16816(c[0],c[1],c[2],c[3], aH[mt][0],aH[mt][1],aH[mt][2],aH[mt][3], bL[nt][0],bL[nt][1]);
                    mma16816(c[0],c[1],c[2],c[3], aL[mt][0],aL[mt][1],aL[mt][2],aL[mt][3], bH[nt][0],bH[nt][1]);
                }
        }
        __syncthreads();
    }
#undef LOAD_STAGE

    size_t zoff = (size_t)blockIdx.z * NNV * NNV;
#pragma unroll
    for (int mt = 0; mt < 4; mt++) {
#pragma unroll
        for (int half = 0; half < 2; half++) {
            int row = row0 + warpM*64 + mt*16 + gr + half*8;
#pragma unroll
            for (int nt = 0; nt < 4; nt++) {
                int col = col0 + warpN*32 + nt*8 + tc*2;
                float2 ov;
                ov.x = acc[mt][nt][half*2 + 0];
                ov.y = acc[mt][nt][half*2 + 1];
                *(float2*)(outF + zoff + (size_t)row*512 + col) = ov;
            }
        }
    }
}

// ====== fused gate+fuse GEMM: 64-row persistent CTA, 4 col tiles x 2 phases ==
#define FARR 8192              // A tile bytes per stage (64 rows x 128B)
#define FSTG 24576             // stage bytes (A 8KB + B 16KB)
#define FSMEM (3*FSTG)         // 73728

__global__ void __launch_bounds__(256, 2) k_gf(
    const __nv_bfloat16* __restrict__ A1, __nv_bfloat16* __restrict__ A2,
    const __nv_bfloat16* __restrict__ B1, const __nv_bfloat16* __restrict__ B2,
    const float* __restrict__ gate_b, const float* __restrict__ fus_b,
    const float* __restrict__ c2v, const float* __restrict__ x,
    float* __restrict__ outH)
{
    extern __shared__ __align__(16) __nv_bfloat16 sm[];
    const uint32_t smb = smem_u32(sm);
    int tid = threadIdx.x;
    int wid = tid >> 5, lane = tid & 31;
    int gr = lane >> 2, tc = lane & 3;
    int warpM = wid >> 2, warpN = wid & 3;
    int row0 = blockIdx.x * 64;

    int aR = warpM*32 + (lane & 15);
    int aKey = aR & 7;
    uint32_t aRow = (uint32_t)aR * 128;
    int aSel = lane >> 4;
    int bR = warpN*32 + (lane & 7);
    int bKey = bR & 7;
    uint32_t bRow = (uint32_t)bR * 128;
    int bSel = (lane >> 3) & 1;

#pragma unroll 1
    for (int phase = 0; phase < 2; phase++) {
        const __nv_bfloat16* Ap = phase ? (const __nv_bfloat16*)A2 : A1;
        const __nv_bfloat16* Bp = phase ? B2 : B1;
#pragma unroll 1
        for (int ct = 0; ct < 4; ct++) {
            int col0 = ct * 128;
            float acc[2][4][4];
#pragma unroll
            for (int mt = 0; mt < 2; mt++)
#pragma unroll
                for (int nt = 0; nt < 4; nt++)
#pragma unroll
                    for (int i = 0; i < 4; i++) acc[mt][nt][i] = 0.f;

#define LOAD_STAGE_F(S) do { \
    uint32_t _sb = smb + (uint32_t)((S) % 3) * FSTG; \
    int _k0 = (S) * 64; \
    _Pragma("unroll") \
    for (int _j = 0; _j < 2; _j++) { \
        int _idx = tid + _j*256; \
        int _r = _idx >> 3, _c = _idx & 7; \
        uint32_t _sw = (uint32_t)(_r*128) + (uint32_t)((_c ^ (_r & 7)) << 4); \
        cp16(_sb + _sw, Ap + (size_t)(row0+_r)*KI + _k0 + _c*8); \
    } \
    _Pragma("unroll") \
    for (int _j = 0; _j < 4; _j++) { \
        int _idx = tid + _j*256; \
        int _r = _idx >> 3, _c = _idx & 7; \
        uint32_t _sw = (uint32_t)(_r*128) + (uint32_t)((_c ^ (_r & 7)) << 4); \
        cp16(_sb + FARR + _sw, Bp + (size_t)(col0+_r)*KI + _k0 + _c*8); \
    } } while (0)

            LOAD_STAGE_F(0);
            asm volatile("cp.async.commit_group;");
            LOAD_STAGE_F(1);
            asm volatile("cp.async.commit_group;");

            for (int s = 0; s < KCH; s++) {
                if (s + 2 < KCH) LOAD_STAGE_F(s + 2);
                asm volatile("cp.async.commit_group;");
                asm volatile("cp.async.wait_group 2;");
                __syncthreads();
                uint32_t bufA = smb + (uint32_t)(s % 3) * FSTG;
                uint32_t bufB = bufA + FARR;
#pragma unroll
                for (int kk = 0; kk < 2; kk++) {
                    int cAh = kk*2 + aSel, cAl = cAh + 4;
                    int cBh = kk*2 + bSel, cBl = cBh + 4;
                    uint32_t aOffH = (uint32_t)((cAh ^ aKey) << 4);
                    uint32_t aOffL = (uint32_t)((cAl ^ aKey) << 4);
                    uint32_t bOffH = (uint32_t)((cBh ^ bKey) << 4);
                    uint32_t bOffL = (uint32_t)((cBl ^ bKey) << 4);
                    uint32_t aH[2][4], aL[2][4];
#pragma unroll
                    for (int mt = 0; mt < 2; mt++) {
                        uint32_t base = bufA + aRow + mt*2048;
                        ldsm_x4(aH[mt], base + aOffH);
                        ldsm_x4(aL[mt], base + aOffL);
                    }
                    uint32_t bH[4][2], bL[4][2];
#pragma unroll
                    for (int nt = 0; nt < 4; nt++) {
                        uint32_t base = bufB + bRow + nt*1024;
                        ldsm_x2(bH[nt], base + bOffH);
                        ldsm_x2(bL[nt], base + bOffL);
                    }
#pragma unroll
                    for (int mt = 0; mt < 2; mt++)
#pragma unroll
                        for (int nt = 0; nt < 4; nt++) {
                            float* c = acc[mt][nt];
                            mma16816(c[0],c[1],c[2],c[3], aH[mt][0],aH[mt][1],aH[mt][2],aH[mt][3], bH[nt][0],bH[nt][1]);
                            mma16816(c[0],c[1],c[2],c[3], aH[mt][0],aH[mt][1],aH[mt][2],aH[mt][3], bL[nt][0],bL[nt][1]);
                            mma16816(c[0],c[1],c[2],c[3], aL[mt][0],aL[mt][1],aL[mt][2],aL[mt][3], bH[nt][0],bH[nt][1]);
                        }
                }
                __syncthreads();
            }
#undef LOAD_STAGE_F

            // ---- epilogue ----
#pragma unroll
            for (int mt = 0; mt < 2; mt++) {
#pragma unroll
                for (int half = 0; half < 2; half++) {
                    int row = row0 + warpM*32 + mt*16 + gr + half*8;
#pragma unroll
                    for (int nt = 0; nt < 4; nt++) {
                        int col = col0 + warpN*32 + nt*8 + tc*2;
                        float c0 = acc[mt][nt][half*2 + 0];
                        float c1 = acc[mt][nt][half*2 + 1];
                        size_t ro = (size_t)row*512 + col;
                        if (phase == 0) {
                            float2 bs = *(const float2*)(gate_b + col);
                            size_t rbase = (size_t)row*KI + (size_t)((col>>5)*64 + (col&31));
                            __nv_bfloat162 hh2 = *(const __nv_bfloat162*)(A1 + rbase);
                            __nv_bfloat162 ll2 = *(const __nv_bfloat162*)(A1 + rbase + 32);
                            float rg0 = __bfloat162float(hh2.x) + __bfloat162float(ll2.x);
                            float rg1 = __bfloat162float(hh2.y) + __bfloat162float(ll2.y);
                            float2 cv = *(const float2*)(c2v + ro);
                            float g0 = 1.f/(1.f + __expf(-(c0 + bs.x)));
                            float g1 = 1.f/(1.f + __expf(-(c1 + bs.y)));
                            float t0 = g0*(rg0 - cv.x);
                            float t1 = g1*(rg1 - cv.y);
                            __nv_bfloat16 h0, l0, h1, l1;
                            bfsplit(t0, h0, l0); bfsplit(t1, h1, l1);
                            __nv_bfloat162 hh; hh.x = h0; hh.y = h1;
                            __nv_bfloat162 llv; llv.x = l0; llv.y = l1;
                            *(__nv_bfloat162*)(A2 + rbase) = hh;
                            *(__nv_bfloat162*)(A2 + rbase + 32) = llv;
                        } else {
                            float2 bs = *(const float2*)(fus_b + col);
                            float2 xv = *(const float2*)(x + ro);
                            float2 hv;
                            hv.x = c0 + bs.x + xv.x;
                            hv.y = c1 + bs.y + xv.y;
                            *(float2*)(outH + ro) = hv;
                        }
                    }
                }
            }
            __syncthreads();   // epilogue writes visible block-wide before reuse
        }
    }
}

// ===================== sim reduce =====================
__global__ void k_simred() {
    int i = blockIdx.x*256 + threadIdx.x;
    if (i >= NNV*NNV) return;
    float s = 0.f;
#pragma unroll
    for (int z = 0; z < SIMZ; z++) s += g_simpart[(size_t)z*NNV*NNV + i];
    g_sim[i] = s;
}

// ===================== top-45 per row (warp per row) =====================
__global__ void k_topk() {
    int warp = threadIdx.x >> 5, lane = threadIdx.x & 31;
    int n = blockIdx.x*4 + warp;
    float v[16];
#pragma unroll
    for (int j = 0; j < 16; j++) {
        int col = j*32 + lane;
        v[j] = (col == n) ? -3.0e38f : g_sim[(size_t)n*NNV + col];
    }
    float lm = -3.0e38f; int li = 0;
#pragma unroll
    for (int j = 0; j < 16; j++) if (v[j] > lm) { lm = v[j]; li = j; }
    for (int it = 0; it < TKV; it++) {
        float m = lm; int src = lane;
#pragma unroll
        for (int o = 16; o; o >>= 1) {
            float om = __shfl_xor_sync(0xffffffffu, m, o);
            int os = __shfl_xor_sync(0xffffffffu, src, o);
            if (om > m || (om == m && os < src)) { m = om; src = os; }
        }
        int wli = __shfl_sync(0xffffffffu, li, src);
        if (lane == 0) g_topk[n*TKV + it] = wli*32 + src;
        if (lane == src) {
#pragma unroll
            for (int j = 0; j < 16; j++) if (j == li) v[j] = -3.0e38f;
            lm = -3.0e38f; li = 0;
#pragma unroll
            for (int j = 0; j < 16; j++) if (v[j] > lm) { lm = v[j]; li = j; }
        }
    }
}

// ===================== per-(b,n) partial sums over L =====================
__global__ void k_partsums(const float* __restrict__ x) {
    int b = blockIdx.x >> 4, ch = blockIdx.x & 15;
    for (int n = threadIdx.x; n < NNV; n += 256) {
        float s = 0.f, q = 0.f;
        const float* p = x + ((size_t)b*LL + ch*128)*NNV + n;
        for (int l = 0; l < 128; l++) { float v = p[(size_t)l*NNV]; s += v; q += v*v; }
        g_ps[(size_t)blockIdx.x*NNV + n] = s;
        g_pq[(size_t)blockIdx.x*NNV + n] = q;
    }
}

// ===================== router head =====================
__global__ void k_router(const float* __restrict__ var_embed,
                         const float* __restrict__ temp_w, const float* __restrict__ temp_b,
                         const float* __restrict__ q_w, const float* __restrict__ q_b,
                         const float* __restrict__ k_w, const float* __restrict__ k_b,
                         const float* __restrict__ imp_w, const float* __restrict__ imp_b) {
    int idx = blockIdx.x*256 + threadIdx.x;
    if (idx >= BB*NNV) return;
    int n = idx & (NNV-1);
    int b = idx >> 9;
    float s = 0.f, q = 0.f;
#pragma unroll
    for (int ch = 0; ch < 16; ch++) {
        s += g_ps[(size_t)(b*16+ch)*NNV + n];
        q += g_pq[(size_t)(b*16+ch)*NNV + n];
    }
    float mean = s * (1.0f/LL);
    float var  = (q - s*mean) * (1.0f/(LL-1));
    float stdv = sqrtf(var + 1e-5f);
    g_summary[idx] = mean;

    float vf[32];
#pragma unroll
    for (int h = 0; h < 16; h++) vf[h] = var_embed[n*16 + h];
#pragma unroll
    for (int h = 0; h < 16; h++) vf[16+h] = mean*temp_w[h] + stdv*temp_w[16+h] + temp_b[h];

    float ip = imp_b[0];
#pragma unroll
    for (int j = 0; j < 32; j++) ip += vf[j]*imp_w[j];
    g_imp[idx] = 1.f/(1.f + expf(-ip));

#pragma unroll
    for (int h = 0; h < 16; h++) {
        float qa = q_b[h], ka = k_b[h];
#pragma unroll
        for (int j = 0; j < 32; j++) { qa += vf[j]*q_w[j*16+h]; ka += vf[j]*k_w[j*16+h]; }
        g_Q[(size_t)idx*16 + h] = qa;
        g_K[(size_t)idx*16 + h] = ka;
    }
}

// ===================== sparse attention softmax =====================
__global__ void k_attn() {
    int w = threadIdx.x >> 5, lane = threadIdx.x & 31;
    int id = blockIdx.x*8 + w;
    int n = id & 511;
    int b = id >> 9;
    float qv[16];
#pragma unroll
    for (int h = 0; h < 16; h++) qv[h] = g_Q[(size_t)id*16 + h];
    int m1 = g_topk[n*TKV + lane];
    float s1 = 0.f;
#pragma unroll
    for (int h = 0; h < 16; h++) s1 += qv[h]*g_K[((size_t)b*512+m1)*16 + h];
    s1 *= 0.25f;
    float s2 = -3.0e38f;
    if (lane < TKV-32) {
        int m2 = g_topk[n*TKV + 32 + lane];
        float t = 0.f;
#pragma unroll
        for (int h = 0; h < 16; h++) t += qv[h]*g_K[((size_t)b*512+m2)*16 + h];
        s2 = t * 0.25f;
    }
    float mx = fmaxf(s1, s2);
#pragma unroll
    for (int o = 16; o; o >>= 1) mx = fmaxf(mx, __shfl_xor_sync(0xffffffffu, mx, o));
    float e1 = expf(s1 - mx);
    float e2 = (lane < TKV-32) ? expf(s2 - mx) : 0.f;
    float sm = e1 + e2;
#pragma unroll
    for (int o = 16; o; o >>= 1) sm += __shfl_xor_sync(0xffffffffu, sm, o);
    float inv = 1.f/sm;
    g_attn[(size_t)id*TKV + lane] = e1*inv;
    if (lane < TKV-32) g_attn[(size_t)id*TKV + 32 + lane] = e2*inv;
}

// ============ ring gather + mix -> A1 interleaved bf16 (float4 LDS) =========
__global__ void __launch_bounds__(512) k_ring(const float* __restrict__ x) {
    __shared__ __align__(16) float xs[512*20];
    int b = blockIdx.y, l0 = blockIdx.x*16;
    const float* xp = x + ((size_t)b*LL + l0)*NNV;
    for (int i = threadIdx.x; i < 16*512; i += 512) {
        int l = i >> 9, n = i & 511;
        xs[n*20 + l] = xp[(size_t)l*NNV + n];
    }
    __syncthreads();
    int n = threadIdx.x;
    float acc[16];
#pragma unroll
    for (int l = 0; l < 16; l++) acc[l] = 0.f;
    size_t abase = ((size_t)b*512 + n)*TKV;
    int ibase = n*TKV;
    const float4* xs4 = (const float4*)xs;
    for (int k = 0; k < TKV; k++) {
        float a = g_attn[abase + k];
        int m = g_topk[ibase + k];
        const float4* xm = xs4 + m*5;
        float4 v0 = xm[0], v1 = xm[1], v2 = xm[2], v3 = xm[3];
        acc[0]  += a*v0.x; acc[1]  += a*v0.y; acc[2]  += a*v0.z; acc[3]  += a*v0.w;
        acc[4]  += a*v1.x; acc[5]  += a*v1.y; acc[6]  += a*v1.z; acc[7]  += a*v1.w;
        acc[8]  += a*v2.x; acc[9]  += a*v2.y; acc[10] += a*v2.z; acc[11] += a*v2.w;
        acc[12] += a*v3.x; acc[13] += a*v3.y; acc[14] += a*v3.z; acc[15] += a*v3.w;
    }
    float imp = g_imp[b*512 + n];
    float omi = 1.f - imp;
    const float* xn = xs + n*20;
    size_t cbase = (size_t)((n>>5)*64 + (n&31));
#pragma unroll
    for (int l = 0; l < 16; l++) {
        size_t row = (size_t)b*LL + l0 + l;
        float v = imp*acc[l] + omi*xn[l];
        __nv_bfloat16 h, lo;
        bfsplit(v, h, lo);
        size_t o = row*KI + cbase;
        g_A1[o] = h;
        g_A1[o+32] = lo;
    }
}

// ===================== cluster weights =====================
__global__ void k_cw(const float* __restrict__ cluster_score) {
    int n = blockIdx.x*256 + threadIdx.x;
    if (n >= NNV) return;
    float v[16], mx = -3e38f;
#pragma unroll
    for (int c = 0; c < 16; c++) { v[c] = cluster_score[n*16+c]; mx = fmaxf(mx, v[c]); }
    float s = 0.f;
#pragma unroll
    for (int c = 0; c < 16; c++) { v[c] = expf(v[c]-mx); s += v[c]; }
    float inv = 1.f/s;
#pragma unroll
    for (int c = 0; c < 16; c++) {
        float e = v[c]*inv;
        g_cw[n*16+c] = e;
        g_cwT[c*512+n] = e;
    }
}

__global__ void k_prep(const float* __restrict__ varproj_w, const float* __restrict__ varproj_b,
                       const float* __restrict__ cp1_w, const float* __restrict__ cp1_b,
                       const float* __restrict__ cp2_w, const float* __restrict__ cp2_b) {
    int tid = threadIdx.x;
    for (int id = tid; id < 1024; id += 256) {
        int c = id >> 6, e = id & 63;
        float s = 0.f;
        for (int d = 0; d < 64; d++) s += varproj_w[c*64+d]*cp1_w[d*64+e];
        g_M1[id] = s;
    }
    if (tid < 64) {
        int e = tid;
        float bbv = cp1_b[e];
        for (int d = 0; d < 64; d++) bbv += varproj_b[d]*cp1_w[d*64+e];
        g_bb[e] = bbv;
        float w2 = 0.f;
        for (int d = 0; d < 64; d++) w2 += cp2_w[e*64+d];
        g_w2[e] = w2;
    }
    if (tid == 0) {
        float s = 0.f;
        for (int d = 0; d < 64; d++) s += cp2_b[d];
        g_b2s = s;
    }
}

// ===== weight transpose + bf16 split + rank-16 fold, interleaved (R8) =====
__global__ void k_prepw(const float* __restrict__ Wd, const float* __restrict__ Wr,
                        __nv_bfloat16* __restrict__ o) {
    __shared__ float colv[512];
    int n = blockIdx.x;
    int tid = threadIdx.x;   // 128
    for (int k = tid; k < 512; k += 128) {
        float w = Wd[(size_t)k*512 + n];
        __nv_bfloat16 h, l;
        bfsplit(w, h, l);
        size_t io = (size_t)n*KI + (size_t)((k>>5)*64 + (k&31));
        o[io] = h;
        o[io+32] = l;
    }
    for (int m = tid; m < 512; m += 128) colv[m] = Wr[(size_t)m*512 + n];
    __syncthreads();
    if (tid < 16) {
        float s = 0.f;
        for (int m = 0; m < 512; m++) s += g_cwT[tid*512 + m]*colv[m];
        __nv_bfloat16 h, l;
        bfsplit(s, h, l);
        size_t io = (size_t)n*KI + 1024 + tid;
        o[io] = h;
        o[io+32] = l;
    } else if (tid < 32) {
        __nv_bfloat16 z = __float2bfloat16(0.f);
        size_t io = (size_t)n*KI + 1024 + tid;
        o[io] = z;
        o[io+32] = z;
    }
}

// ===================== center tokens + projection =====================
__global__ void k_ct(const float* __restrict__ cg_w, const float* __restrict__ cg_b) {
    int b = blockIdx.x;
    int j = blockIdx.y*256 + threadIdx.x;
    float s = cg_b[j];
    for (int n = 0; n < NNV; n++) s += g_summary[b*512+n]*cg_w[(size_t)n*1024 + j];
    g_ct[b*1024 + j] = s;
}

__global__ void k_ctp(const float* __restrict__ cp1_w) {
    int id = blockIdx.x*256 + threadIdx.x;
    if (id >= BB*16*64) return;
    int b = id >> 10;
    int cd = id & 1023;
    int c = cd >> 6, e = cd & 63;
    float s = 0.f;
    for (int d = 0; d < 64; d++) s += g_ct[b*1024 + c*64 + d]*cp1_w[d*64+e];
    g_ctp[id] = s;
}

// ===================== xcs = x @ cw =====================
__global__ void k_xcs(const float* __restrict__ x) {
    __shared__ float xs[16*512];
    int row0 = blockIdx.x*16;
    const float* xp = x + (size_t)row0*NNV;
    for (int i = threadIdx.x; i < 16*512; i += 256) xs[i] = xp[i];
    __syncthreads();
    int l = threadIdx.x >> 4, c = threadIdx.x & 15;
    float s = 0.f;
    for (int n = 0; n < NNV; n++) s += xs[l*512+n]*__ldg(&g_cw[n*16+c]);
    g_xcs[(size_t)(row0+l)*16 + c] = s;
}

// ========== Sc (gelu-folded) + c2v + Sc K-extension (interleaved) ==========
__global__ void k_scc2v() {
    __shared__ float sxc[16], sx[64], red[128], sSc[16];
    size_t bl = blockIdx.x;
    int b = (int)(bl >> 11);
    int tid = threadIdx.x;
    if (tid < 16) sxc[tid] = g_xcs[bl*16 + tid];
    __syncthreads();
    if (tid < 64) {
        float s = g_bb[tid];
#pragma unroll
        for (int c = 0; c < 16; c++) s += sxc[c]*g_M1[c*64 + tid];
        sx[tid] = s;
    }
    __syncthreads();
    int c = tid >> 3, gi = tid & 7;
    float p = 0.f;
    const float* ctp = &g_ctp[(size_t)b*1024 + c*64];
#pragma unroll
    for (int ee = 0; ee < 8; ee++) {
        int e = gi*8 + ee;
        float t = sx[e] + ctp[e];
        p += (0.5f*t*(1.f + erff(t*0.70710678118654752f)))*g_w2[e];
    }
    red[tid] = p;
    __syncthreads();
    if (tid < 16) {
        float s = g_b2s;
#pragma unroll
        for (int gg = 0; gg < 8; gg++) s += red[tid*8 + gg];
        sSc[tid] = s;
    }
    __syncthreads();
    if (tid < 16) {
        float v = sSc[tid];
        __nv_bfloat16 h, l;
        bfsplit(v, h, l);
        size_t o = bl*KI + 1024 + tid;
        g_A1[o] = h; g_A1[o+32] = l;
        g_A2[o] = h; g_A2[o+32] = l;
    } else if (tid < 32) {
        __nv_bfloat16 z = __float2bfloat16(0.f);
        size_t o = bl*KI + 1024 + tid;
        g_A1[o] = z; g_A1[o+32] = z;
        g_A2[o] = z; g_A2[o+32] = z;
    }
    float sc[16];
#pragma unroll
    for (int cc = 0; cc < 16; cc++) sc[cc] = sSc[cc];
    float* op = &g_c2v[bl*NNV];
    for (int n = tid; n < NNV; n += 128) {
        float a = 0.f;
#pragma unroll
        for (int cc = 0; cc < 16; cc++) a += sc[cc]*__ldg(&g_cwT[cc*512 + n]);
        op[n] = a;
    }
}

// ===================== layernorm =====================
__global__ void k_ln(const float* __restrict__ lng, const float* __restrict__ lnb,
                     float* __restrict__ out) {
    __shared__ float ss[4], sq[4];
    int row = blockIdx.x, tid = threadIdx.x;
    float4 h4 = ((const float4*)(g_h + (size_t)row*NNV))[tid];
    float s = h4.x + h4.y + h4.z + h4.w;
    float q = h4.x*h4.x + h4.y*h4.y + h4.z*h4.z + h4.w*h4.w;
#pragma unroll
    for (int o = 16; o; o >>= 1) {
        s += __shfl_xor_sync(0xffffffffu, s, o);
        q += __shfl_xor_sync(0xffffffffu, q, o);
    }
    if ((tid & 31) == 0) { ss[tid>>5] = s; sq[tid>>5] = q; }
    __syncthreads();
    s = ss[0] + ss[1] + ss[2] + ss[3];
    q = sq[0] + sq[1] + sq[2] + sq[3];
    float mu = s*(1.f/NNV);
    float var = q*(1.f/NNV) - mu*mu;
    float inv = rsqrtf(var + 1e-5f);
    float4 g4 = ((const float4*)lng)[tid];
    float4 b4 = ((const float4*)lnb)[tid];
    float4 o4;
    o4.x = (h4.x - mu)*inv*g4.x + b4.x;
    o4.y = (h4.y - mu)*inv*g4.y + b4.y;
    o4.z = (h4.z - mu)*inv*g4.z + b4.z;
    o4.w = (h4.w - mu)*inv*g4.w + b4.w;
    ((float4*)(out + (size_t)row*NNV))[tid] = o4;
}

// ========== launch (3 created streams + default main chain, R8 topology) =====
extern "C" void kernel_launch(void* const* d_in, const int* in_sizes, int n_in,
                              void* d_out, int out_size) {
    const float* x          = (const float*)d_in[0];
    const float* var_embed  = (const float*)d_in[1];
    const float* temp_w     = (const float*)d_in[2];
    const float* temp_b     = (const float*)d_in[3];
    const float* q_w        = (const float*)d_in[4];
    const float* q_b        = (const float*)d_in[5];
    const float* k_w        = (const float*)d_in[6];
    const float* k_b        = (const float*)d_in[7];
    const float* imp_w      = (const float*)d_in[8];
    const float* imp_b      = (const float*)d_in[9];
    const float* cluster_sc = (const float*)d_in[10];
    const float* varproj_w  = (const float*)d_in[11];
    const float* varproj_b  = (const float*)d_in[12];
    const float* cp1_w      = (const float*)d_in[13];
    const float* cp1_b      = (const float*)d_in[14];
    const float* cp2_w      = (const float*)d_in[15];
    const float* cp2_b      = (const float*)d_in[16];
    const float* cg_w       = (const float*)d_in[17];
    const float* cg_b       = (const float*)d_in[18];
    const float* gate_w     = (const float*)d_in[19];
    const float* gate_b     = (const float*)d_in[20];
    const float* fus_w      = (const float*)d_in[21];
    const float* fus_b      = (const float*)d_in[22];
    const float* ln_g       = (const float*)d_in[23];
    const float* ln_b       = (const float*)d_in[24];
    float* out = (float*)d_out;

    float *p_c2v, *p_h, *p_simpart;
    __nv_bfloat16 *pA1, *pA2, *pB1, *pB2, *pnT;
    cudaGetSymbolAddress((void**)&p_c2v,  g_c2v);
    cudaGetSymbolAddress((void**)&p_h,    g_h);
    cudaGetSymbolAddress((void**)&p_simpart, g_simpart);
    cudaGetSymbolAddress((void**)&pA1, g_A1);
    cudaGetSymbolAddress((void**)&pA2, g_A2);
    cudaGetSymbolAddress((void**)&pB1, g_B1);
    cudaGetSymbolAddress((void**)&pB2, g_B2);
    cudaGetSymbolAddress((void**)&pnT, g_nT);

    const int GSMEM = 3 * STAGEB;   // 98304 bytes
    cudaFuncSetAttribute(k_gsim, cudaFuncAttributeMaxDynamicSharedMemorySize, GSMEM);
    cudaFuncSetAttribute(k_gf,   cudaFuncAttributeMaxDynamicSharedMemorySize, FSMEM);

    static cudaStream_t sA = nullptr, sB = nullptr, sC = nullptr;
    static cudaEvent_t evRoot, evTopk, evRouter, evCw, evSB, evSC;
    if (sA == nullptr) {
        cudaStreamCreateWithFlags(&sA, cudaStreamNonBlocking);
        cudaStreamCreateWithFlags(&sB, cudaStreamNonBlocking);
        cudaStreamCreateWithFlags(&sC, cudaStreamNonBlocking);
        cudaEventCreateWithFlags(&evRoot,   cudaEventDisableTiming);
        cudaEventCreateWithFlags(&evTopk,   cudaEventDisableTiming);
        cudaEventCreateWithFlags(&evRouter, cudaEventDisableTiming);
        cudaEventCreateWithFlags(&evCw,     cudaEventDisableTiming);
        cudaEventCreateWithFlags(&evSB,     cudaEventDisableTiming);
        cudaEventCreateWithFlags(&evSC,     cudaEventDisableTiming);
    }

    cudaEventRecord(evRoot, 0);

    // ---- stream A: mask path (critical) ----
    cudaStreamWaitEvent(sA, evRoot, 0);
    k_colstats<<<dim3(LL/64, NNV/64), 256, 0, sA>>>(x);
    k_gsim<<<dim3(4,4,SIMZ), 256, GSMEM, sA>>>(pnT, NTI, (LL/SIMZ)/32, (LL/SIMZ)/32,
                                               p_simpart);
    k_simred<<<NNV*NNV/256, 256, 0, sA>>>();
    k_topk<<<NNV/4, 128, 0, sA>>>();
    cudaEventRecord(evTopk, sA);

    // ---- stream C: cluster weights + weight prep ----
    cudaStreamWaitEvent(sC, evRoot, 0);
    k_cw<<<2, 256, 0, sC>>>(cluster_sc);
    k_prep<<<1, 256, 0, sC>>>(varproj_w, varproj_b, cp1_w, cp1_b, cp2_w, cp2_b);
    cudaEventRecord(evCw, sC);
    k_prepw<<<512, 128, 0, sC>>>(gate_w, gate_w + 512*512, pB1);
    k_prepw<<<512, 128, 0, sC>>>(fus_w, fus_w, pB2);
    cudaEventRecord(evSC, sC);

    // ---- stream B: router stats + center path ----
    cudaStreamWaitEvent(sB, evRoot, 0);
    k_partsums<<<BB*16, 256, 0, sB>>>(x);
    k_router<<<BB*NNV/256, 256, 0, sB>>>(var_embed, temp_w, temp_b, q_w, q_b, k_w, k_b, imp_w, imp_b);
    cudaEventRecord(evRouter, sB);
    cudaStreamWaitEvent(sB, evCw, 0);
    k_ct<<<dim3(BB, 4), 256, 0, sB>>>(cg_w, cg_b);
    k_ctp<<<BB*16*64/256, 256, 0, sB>>>(cp1_w);
    k_xcs<<<BLV/16, 256, 0, sB>>>(x);
    k_scc2v<<<BLV, 128, 0, sB>>>();
    cudaEventRecord(evSB, sB);

    // ---- default stream: attention -> ring -> fused GEMMs -> LN ----
    cudaStreamWaitEvent(0, evTopk, 0);
    cudaStreamWaitEvent(0, evRouter, 0);
    k_attn<<<BB*NNV/8, 256>>>();
    k_ring<<<dim3(LL/16, BB), 512>>>(x);
    cudaStreamWaitEvent(0, evSB, 0);
    cudaStreamWaitEvent(0, evSC, 0);
    k_gf<<<BLV/64, 256, FSMEM>>>(pA1, pA2, pB1, pB2, gate_b, fus_b, p_c2v, x, p_h);
    k_ln<<<BLV, 128>>>(ln_g, ln_b, out);

    (void)in_sizes; (void)n_in; (void)out_size;
}

// round 16
// speedup vs baseline: 1.1020x; 1.1020x over previous
#include <cuda_runtime.h>
#include <cuda_bf16.h>
#include <math.h>
#include <stddef.h>
#include <stdint.h>

#define BB 8
#define LL 2048
#define NNV 512
#define HHV 16
#define CCV 16
#define DDV 64
#define TKV 45
#define BLV (BB*LL)
#define KCH 17                 // 544/32 chunks (512 data + 16 fold + 16 pad)
#define KI (KCH*64)            // 1088 interleaved elems per row (hi|lo per 32-chunk)
#define NTI ((LL/32)*64)       // 4096 interleaved elems per row for sim operand
#define SIMZ 8

__device__ __forceinline__ void bfsplit(float v, __nv_bfloat16& h, __nv_bfloat16& l) {
    h = __float2bfloat16(v);
    l = __float2bfloat16(v - __bfloat162float(h));
}
__device__ __forceinline__ void mma16816(float& c0, float& c1, float& c2, float& c3,
                                         uint32_t a0, uint32_t a1, uint32_t a2, uint32_t a3,
                                         uint32_t b0, uint32_t b1) {
    asm volatile(
        "mma.sync.aligned.m16n8k16.row.col.f32.bf16.bf16.f32 "
        "{%0,%1,%2,%3}, {%4,%5,%6,%7}, {%8,%9}, {%0,%1,%2,%3};"
        : "+f"(c0), "+f"(c1), "+f"(c2), "+f"(c3)
        : "r"(a0), "r"(a1), "r"(a2), "r"(a3), "r"(b0), "r"(b1));
}
__device__ __forceinline__ uint32_t smem_u32(const void* p) {
    uint32_t a;
    asm("{ .reg .u64 t; cvta.to.shared.u64 t, %1; cvt.u32.u64 %0, t; }" : "=r"(a) : "l"(p));
    return a;
}
__device__ __forceinline__ void cp16(uint32_t dst, const void* src) {
    asm volatile("cp.async.cg.shared.global [%0], [%1], 16;" :: "r"(dst), "l"(src));
}
__device__ __forceinline__ void ldsm_x4(uint32_t* r, uint32_t addr) {
    asm volatile("ldmatrix.sync.aligned.m8n8.x4.shared.b16 {%0,%1,%2,%3}, [%4];"
                 : "=r"(r[0]), "=r"(r[1]), "=r"(r[2]), "=r"(r[3]) : "r"(addr));
}
__device__ __forceinline__ void ldsm_x2(uint32_t* r, uint32_t addr) {
    asm volatile("ldmatrix.sync.aligned.m8n8.x2.shared.b16 {%0,%1}, [%2];"
                 : "=r"(r[0]), "=r"(r[1]) : "r"(addr));
}

// ===================== scratch (device globals) =====================
__device__ float g_simpart[SIMZ*NNV*NNV];
__device__ float g_sim[NNV*NNV];
__device__ int   g_topk[NNV*TKV];
__device__ float g_attn[BB*NNV*TKV];
__device__ float g_Q[BB*NNV*HHV];
__device__ float g_K[BB*NNV*HHV];
__device__ float g_imp[BB*NNV];
__device__ float g_summary[BB*NNV];
__device__ float g_ps[BB*16*NNV];
__device__ float g_pq[BB*16*NNV];
__device__ float g_cw[NNV*CCV];
__device__ float g_cwT[CCV*NNV];
__device__ float g_M1[CCV*DDV];
__device__ float g_bb[DDV];
__device__ float g_w2[DDV];
__device__ float g_b2s;
__device__ float g_ct[BB*CCV*DDV];
__device__ float g_ctp[BB*CCV*DDV];
__device__ float g_xcs[(size_t)BLV*CCV];
__device__ float g_c2v[(size_t)BLV*NNV];
__device__ float g_h[(size_t)BLV*NNV];
__device__ __align__(16) __nv_bfloat16 g_nT[(size_t)NNV*NTI];
__device__ __align__(16) __nv_bfloat16 g_A1[(size_t)BLV*KI];
__device__ __align__(16) __nv_bfloat16 g_A2[(size_t)BLV*KI];
__device__ __align__(16) __nv_bfloat16 g_B1[(size_t)NNV*KI];
__device__ __align__(16) __nv_bfloat16 g_B2[(size_t)NNV*KI];

// ========== 1. column stats -> normedT interleaved hi/lo (smem transpose) ====
__global__ void k_colstats(const float* __restrict__ x) {
    __shared__ float tile[64][65];
    int l0 = blockIdx.x*64, n0 = blockIdx.y*64;
    int tid = threadIdx.x;
#pragma unroll
    for (int it = 0; it < 16; it++) {
        int id = it*256 + tid;
        int dl = id >> 6, dn = id & 63;
        size_t off = (size_t)(l0+dl)*NNV + n0 + dn;
        float v[BB];
#pragma unroll
        for (int b = 0; b < BB; b++) v[b] = x[(size_t)b*LL*NNV + off];
        float s = 0.f;
#pragma unroll
        for (int b = 0; b < BB; b++) s += v[b];
        float mean = s * (1.0f/BB);
        float q = 0.f;
#pragma unroll
        for (int b = 0; b < BB; b++) { float d = v[b]-mean; q += d*d; }
        float stdv = sqrtf(q * (1.0f/(BB-1))) + 1e-5f;
        tile[dn][dl] = mean / stdv;
    }
    __syncthreads();
#pragma unroll
    for (int it = 0; it < 16; it++) {
        int id = it*256 + tid;
        int dn = id >> 6, dl = id & 63;
        float v = tile[dn][dl];
        __nv_bfloat16 h, lo;
        bfsplit(v, h, lo);
        int l = l0 + dl;
        size_t o = (size_t)(n0+dn)*NTI + (size_t)(l>>5)*64 + (l&31);
        g_nT[o] = h;
        g_nT[o+32] = lo;
    }
}

// ========= sim GEMM: 3-stage pipelined 3-pass bf16 HMMA (SW128, R8) ==========
#define STAGEB 32768

__global__ void __launch_bounds__(256, 2) k_gsim(
    const __nv_bfloat16* __restrict__ A, int lda, int kz32, int nStages,
    float* __restrict__ outF)
{
    extern __shared__ __align__(16) __nv_bfloat16 sm[];
    const uint32_t smb = smem_u32(sm);
    int tid = threadIdx.x;
    int wid = tid >> 5, lane = tid & 31;
    int gr = lane >> 2, tc = lane & 3;
    int warpM = wid >> 2, warpN = wid & 3;
    int row0 = blockIdx.y * 128, col0 = blockIdx.x * 128;
    int kStart32 = blockIdx.z * kz32;

    float acc[4][4][4];
#pragma unroll
    for (int mt = 0; mt < 4; mt++)
#pragma unroll
        for (int nt = 0; nt < 4; nt++)
#pragma unroll
            for (int i = 0; i < 4; i++) acc[mt][nt][i] = 0.f;

    int aR = warpM*64 + (lane & 15);
    int aKey = aR & 7;
    uint32_t aRow = (uint32_t)aR * 128;
    int aSel = lane >> 4;
    int bR = warpN*32 + (lane & 7);
    int bKey = bR & 7;
    uint32_t bRow = (uint32_t)bR * 128;
    int bSel = (lane >> 3) & 1;

#define LOAD_STAGE(S) do { \
    uint32_t _sb = smb + (uint32_t)((S) % 3) * STAGEB; \
    int _k0 = (kStart32 + (S)) * 64; \
    _Pragma("unroll") \
    for (int _j = 0; _j < 4; _j++) { \
        int _idx = tid + _j*256; \
        int _r = _idx >> 3, _c = _idx & 7; \
        uint32_t _sw = (uint32_t)(_r*128) + (uint32_t)((_c ^ (_r & 7)) << 4); \
        cp16(_sb + _sw,         A + (size_t)(row0+_r)*lda + _k0 + _c*8); \
        cp16(_sb + 16384 + _sw, A + (size_t)(col0+_r)*lda + _k0 + _c*8); \
    } } while (0)

    LOAD_STAGE(0);
    asm volatile("cp.async.commit_group;");
    if (nStages > 1) LOAD_STAGE(1);
    asm volatile("cp.async.commit_group;");

    for (int s = 0; s < nStages; s++) {
        if (s + 2 < nStages) LOAD_STAGE(s + 2);
        asm volatile("cp.async.commit_group;");
        asm volatile("cp.async.wait_group 2;");
        __syncthreads();
        uint32_t bufA = smb + (uint32_t)(s % 3) * STAGEB;
        uint32_t bufB = bufA + 16384;
#pragma unroll
        for (int kk = 0; kk < 2; kk++) {
            int cAh = kk*2 + aSel, cAl = cAh + 4;
            int cBh = kk*2 + bSel, cBl = cBh + 4;
            uint32_t aOffH = (uint32_t)((cAh ^ aKey) << 4);
            uint32_t aOffL = (uint32_t)((cAl ^ aKey) << 4);
            uint32_t bOffH = (uint32_t)((cBh ^ bKey) << 4);
            uint32_t bOffL = (uint32_t)((cBl ^ bKey) << 4);
            uint32_t aH[4][4], aL[4][4];
#pragma unroll
            for (int mt = 0; mt < 4; mt++) {
                uint32_t base = bufA + aRow + mt*2048;
                ldsm_x4(aH[mt], base + aOffH);
                ldsm_x4(aL[mt], base + aOffL);
            }
            uint32_t bH[4][2], bL[4][2];
#pragma unroll
            for (int nt = 0; nt < 4; nt++) {
                uint32_t base = bufB + bRow + nt*1024;
                ldsm_x2(bH[nt], base + bOffH);
                ldsm_x2(bL[nt], base + bOffL);
            }
#pragma unroll
            for (int mt = 0; mt < 4; mt++)
#pragma unroll
                for (int nt = 0; nt < 4; nt++) {
                    float* c = acc[mt][nt];
                    mma16816(c[0],c[1],c[2],c[3], aH[mt][0],aH[mt][1],aH[mt][2],aH[mt][3], bH[nt][0],bH[nt][1]);
                    mma16816(c[0],c[1],c[2],c[3], aH[mt][0],aH[mt][1],aH[mt][2],aH[mt][3], bL[nt][0],bL[nt][1]);
                    mma16816(c[0],c[1],c[2],c[3], aL[mt][0],aL[mt][1],aL[mt][2],aL[mt][3], bH[nt][0],bH[nt][1]);
                }
        }
        __syncthreads();
    }
#undef LOAD_STAGE

    size_t zoff = (size_t)blockIdx.z * NNV * NNV;
#pragma unroll
    for (int mt = 0; mt < 4; mt++) {
#pragma unroll
        for (int half = 0; half < 2; half++) {
            int row = row0 + warpM*64 + mt*16 + gr + half*8;
#pragma unroll
            for (int nt = 0; nt < 4; nt++) {
                int col = col0 + warpN*32 + nt*8 + tc*2;
                float2 ov;
                ov.x = acc[mt][nt][half*2 + 0];
                ov.y = acc[mt][nt][half*2 + 1];
                *(float2*)(outF + zoff + (size_t)row*512 + col) = ov;
            }
        }
    }
}

// == fused gate+fuse GEMM + LayerNorm: 64-row persistent CTA, 4 col tiles x 2 ==
#define FARR 8192              // A tile bytes per stage (64 rows x 128B)
#define FSTG 24576             // stage bytes (A 8KB + B 16KB)
#define FSMEM (3*FSTG)         // 73728

__global__ void __launch_bounds__(256, 2) k_gf(
    const __nv_bfloat16* __restrict__ A1, __nv_bfloat16* __restrict__ A2,
    const __nv_bfloat16* __restrict__ B1, const __nv_bfloat16* __restrict__ B2,
    const float* __restrict__ gate_b, const float* __restrict__ fus_b,
    const float* __restrict__ c2v, const float* __restrict__ x,
    float* __restrict__ outH,
    const float* __restrict__ lng, const float* __restrict__ lnb,
    float* __restrict__ outFinal)
{
    extern __shared__ __align__(16) __nv_bfloat16 sm[];
    const uint32_t smb = smem_u32(sm);
    int tid = threadIdx.x;
    int wid = tid >> 5, lane = tid & 31;
    int gr = lane >> 2, tc = lane & 3;
    int warpM = wid >> 2, warpN = wid & 3;
    int row0 = blockIdx.x * 64;

    int aR = warpM*32 + (lane & 15);
    int aKey = aR & 7;
    uint32_t aRow = (uint32_t)aR * 128;
    int aSel = lane >> 4;
    int bR = warpN*32 + (lane & 7);
    int bKey = bR & 7;
    uint32_t bRow = (uint32_t)bR * 128;
    int bSel = (lane >> 3) & 1;

#pragma unroll 1
    for (int phase = 0; phase < 2; phase++) {
        const __nv_bfloat16* Ap = phase ? (const __nv_bfloat16*)A2 : A1;
        const __nv_bfloat16* Bp = phase ? B2 : B1;
#pragma unroll 1
        for (int ct = 0; ct < 4; ct++) {
            int col0 = ct * 128;
            float acc[2][4][4];
#pragma unroll
            for (int mt = 0; mt < 2; mt++)
#pragma unroll
                for (int nt = 0; nt < 4; nt++)
#pragma unroll
                    for (int i = 0; i < 4; i++) acc[mt][nt][i] = 0.f;

#define LOAD_STAGE_F(S) do { \
    uint32_t _sb = smb + (uint32_t)((S) % 3) * FSTG; \
    int _k0 = (S) * 64; \
    _Pragma("unroll") \
    for (int _j = 0; _j < 2; _j++) { \
        int _idx = tid + _j*256; \
        int _r = _idx >> 3, _c = _idx & 7; \
        uint32_t _sw = (uint32_t)(_r*128) + (uint32_t)((_c ^ (_r & 7)) << 4); \
        cp16(_sb + _sw, Ap + (size_t)(row0+_r)*KI + _k0 + _c*8); \
    } \
    _Pragma("unroll") \
    for (int _j = 0; _j < 4; _j++) { \
        int _idx = tid + _j*256; \
        int _r = _idx >> 3, _c = _idx & 7; \
        uint32_t _sw = (uint32_t)(_r*128) + (uint32_t)((_c ^ (_r & 7)) << 4); \
        cp16(_sb + FARR + _sw, Bp + (size_t)(col0+_r)*KI + _k0 + _c*8); \
    } } while (0)

            LOAD_STAGE_F(0);
            asm volatile("cp.async.commit_group;");
            LOAD_STAGE_F(1);
            asm volatile("cp.async.commit_group;");

            for (int s = 0; s < KCH; s++) {
                if (s + 2 < KCH) LOAD_STAGE_F(s + 2);
                asm volatile("cp.async.commit_group;");
                asm volatile("cp.async.wait_group 2;");
                __syncthreads();
                uint32_t bufA = smb + (uint32_t)(s % 3) * FSTG;
                uint32_t bufB = bufA + FARR;
#pragma unroll
                for (int kk = 0; kk < 2; kk++) {
                    int cAh = kk*2 + aSel, cAl = cAh + 4;
                    int cBh = kk*2 + bSel, cBl = cBh + 4;
                    uint32_t aOffH = (uint32_t)((cAh ^ aKey) << 4);
                    uint32_t aOffL = (uint32_t)((cAl ^ aKey) << 4);
                    uint32_t bOffH = (uint32_t)((cBh ^ bKey) << 4);
                    uint32_t bOffL = (uint32_t)((cBl ^ bKey) << 4);
                    uint32_t aH[2][4], aL[2][4];
#pragma unroll
                    for (int mt = 0; mt < 2; mt++) {
                        uint32_t base = bufA + aRow + mt*2048;
                        ldsm_x4(aH[mt], base + aOffH);
                        ldsm_x4(aL[mt], base + aOffL);
                    }
                    uint32_t bH[4][2], bL[4][2];
#pragma unroll
                    for (int nt = 0; nt < 4; nt++) {
                        uint32_t base = bufB + bRow + nt*1024;
                        ldsm_x2(bH[nt], base + bOffH);
                        ldsm_x2(bL[nt], base + bOffL);
                    }
#pragma unroll
                    for (int mt = 0; mt < 2; mt++)
#pragma unroll
                        for (int nt = 0; nt < 4; nt++) {
                            float* c = acc[mt][nt];
                            mma16816(c[0],c[1],c[2],c[3], aH[mt][0],aH[mt][1],aH[mt][2],aH[mt][3], bH[nt][0],bH[nt][1]);
                            mma16816(c[0],c[1],c[2],c[3], aH[mt][0],aH[mt][1],aH[mt][2],aH[mt][3], bL[nt][0],bL[nt][1]);
                            mma16816(c[0],c[1],c[2],c[3], aL[mt][0],aL[mt][1],aL[mt][2],aL[mt][3], bH[nt][0],bH[nt][1]);
                        }
                }
                __syncthreads();
            }
#undef LOAD_STAGE_F

            // ---- epilogue ----
#pragma unroll
            for (int mt = 0; mt < 2; mt++) {
#pragma unroll
                for (int half = 0; half < 2; half++) {
                    int row = row0 + warpM*32 + mt*16 + gr + half*8;
#pragma unroll
                    for (int nt = 0; nt < 4; nt++) {
                        int col = col0 + warpN*32 + nt*8 + tc*2;
                        float c0 = acc[mt][nt][half*2 + 0];
                        float c1 = acc[mt][nt][half*2 + 1];
                        size_t ro = (size_t)row*512 + col;
                        if (phase == 0) {
                            float2 bs = *(const float2*)(gate_b + col);
                            size_t rbase = (size_t)row*KI + (size_t)((col>>5)*64 + (col&31));
                            __nv_bfloat162 hh2 = *(const __nv_bfloat162*)(A1 + rbase);
                            __nv_bfloat162 ll2 = *(const __nv_bfloat162*)(A1 + rbase + 32);
                            float rg0 = __bfloat162float(hh2.x) + __bfloat162float(ll2.x);
                            float rg1 = __bfloat162float(hh2.y) + __bfloat162float(ll2.y);
                            float2 cv = *(const float2*)(c2v + ro);
                            float g0 = 1.f/(1.f + __expf(-(c0 + bs.x)));
                            float g1 = 1.f/(1.f + __expf(-(c1 + bs.y)));
                            float t0 = g0*(rg0 - cv.x);
                            float t1 = g1*(rg1 - cv.y);
                            __nv_bfloat16 h0, l0, h1, l1;
                            bfsplit(t0, h0, l0); bfsplit(t1, h1, l1);
                            __nv_bfloat162 hh; hh.x = h0; hh.y = h1;
                            __nv_bfloat162 llv; llv.x = l0; llv.y = l1;
                            *(__nv_bfloat162*)(A2 + rbase) = hh;
                            *(__nv_bfloat162*)(A2 + rbase + 32) = llv;
                        } else {
                            float2 bs = *(const float2*)(fus_b + col);
                            float2 xv = *(const float2*)(x + ro);
                            float2 hv;
                            hv.x = c0 + bs.x + xv.x;
                            hv.y = c1 + bs.y + xv.y;
                            *(float2*)(outH + ro) = hv;
                        }
                    }
                }
            }
            __syncthreads();   // epilogue writes visible block-wide before reuse
        }
    }

    // ---- fused LayerNorm over this CTA's 64 rows (h is L2-hot) ----
    // 8 warps x 8 rows each; per row 512 floats = 4 float4 per lane.
#pragma unroll 1
    for (int r8 = 0; r8 < 8; r8++) {
        int row = row0 + wid*8 + r8;
        const float4* hp = (const float4*)(outH + (size_t)row*NNV);
        float4 hv[4];
#pragma unroll
        for (int k = 0; k < 4; k++) hv[k] = hp[lane + k*32];
        float s = 0.f, q = 0.f;
#pragma unroll
        for (int k = 0; k < 4; k++) {
            s += hv[k].x + hv[k].y + hv[k].z + hv[k].w;
            q += hv[k].x*hv[k].x + hv[k].y*hv[k].y + hv[k].z*hv[k].z + hv[k].w*hv[k].w;
        }
#pragma unroll
        for (int o = 16; o; o >>= 1) {
            s += __shfl_xor_sync(0xffffffffu, s, o);
            q += __shfl_xor_sync(0xffffffffu, q, o);
        }
        float mu = s*(1.f/NNV);
        float var = q*(1.f/NNV) - mu*mu;
        float inv = rsqrtf(var + 1e-5f);
        float4* op = (float4*)(outFinal + (size_t)row*NNV);
#pragma unroll
        for (int k = 0; k < 4; k++) {
            int col4 = lane + k*32;
            float4 g4 = ((const float4*)lng)[col4];
            float4 b4 = ((const float4*)lnb)[col4];
            float4 o4;
            o4.x = (hv[k].x - mu)*inv*g4.x + b4.x;
            o4.y = (hv[k].y - mu)*inv*g4.y + b4.y;
            o4.z = (hv[k].z - mu)*inv*g4.z + b4.z;
            o4.w = (hv[k].w - mu)*inv*g4.w + b4.w;
            op[col4] = o4;
        }
    }
}

// ===================== sim reduce =====================
__global__ void k_simred() {
    int i = blockIdx.x*256 + threadIdx.x;
    if (i >= NNV*NNV) return;
    float s = 0.f;
#pragma unroll
    for (int z = 0; z < SIMZ; z++) s += g_simpart[(size_t)z*NNV*NNV + i];
    g_sim[i] = s;
}

// ===================== top-45 per row (warp per row) =====================
__global__ void k_topk() {
    int warp = threadIdx.x >> 5, lane = threadIdx.x & 31;
    int n = blockIdx.x*4 + warp;
    float v[16];
#pragma unroll
    for (int j = 0; j < 16; j++) {
        int col = j*32 + lane;
        v[j] = (col == n) ? -3.0e38f : g_sim[(size_t)n*NNV + col];
    }
    float lm = -3.0e38f; int li = 0;
#pragma unroll
    for (int j = 0; j < 16; j++) if (v[j] > lm) { lm = v[j]; li = j; }
    for (int it = 0; it < TKV; it++) {
        float m = lm; int src = lane;
#pragma unroll
        for (int o = 16; o; o >>= 1) {
            float om = __shfl_xor_sync(0xffffffffu, m, o);
            int os = __shfl_xor_sync(0xffffffffu, src, o);
            if (om > m || (om == m && os < src)) { m = om; src = os; }
        }
        int wli = __shfl_sync(0xffffffffu, li, src);
        if (lane == 0) g_topk[n*TKV + it] = wli*32 + src;
        if (lane == src) {
#pragma unroll
            for (int j = 0; j < 16; j++) if (j == li) v[j] = -3.0e38f;
            lm = -3.0e38f; li = 0;
#pragma unroll
            for (int j = 0; j < 16; j++) if (v[j] > lm) { lm = v[j]; li = j; }
        }
    }
}

// ===================== per-(b,n) partial sums over L =====================
__global__ void k_partsums(const float* __restrict__ x) {
    int b = blockIdx.x >> 4, ch = blockIdx.x & 15;
    for (int n = threadIdx.x; n < NNV; n += 256) {
        float s = 0.f, q = 0.f;
        const float* p = x + ((size_t)b*LL + ch*128)*NNV + n;
        for (int l = 0; l < 128; l++) { float v = p[(size_t)l*NNV]; s += v; q += v*v; }
        g_ps[(size_t)blockIdx.x*NNV + n] = s;
        g_pq[(size_t)blockIdx.x*NNV + n] = q;
    }
}

// ===================== router head =====================
__global__ void k_router(const float* __restrict__ var_embed,
                         const float* __restrict__ temp_w, const float* __restrict__ temp_b,
                         const float* __restrict__ q_w, const float* __restrict__ q_b,
                         const float* __restrict__ k_w, const float* __restrict__ k_b,
                         const float* __restrict__ imp_w, const float* __restrict__ imp_b) {
    int idx = blockIdx.x*256 + threadIdx.x;
    if (idx >= BB*NNV) return;
    int n = idx & (NNV-1);
    int b = idx >> 9;
    float s = 0.f, q = 0.f;
#pragma unroll
    for (int ch = 0; ch < 16; ch++) {
        s += g_ps[(size_t)(b*16+ch)*NNV + n];
        q += g_pq[(size_t)(b*16+ch)*NNV + n];
    }
    float mean = s * (1.0f/LL);
    float var  = (q - s*mean) * (1.0f/(LL-1));
    float stdv = sqrtf(var + 1e-5f);
    g_summary[idx] = mean;

    float vf[32];
#pragma unroll
    for (int h = 0; h < 16; h++) vf[h] = var_embed[n*16 + h];
#pragma unroll
    for (int h = 0; h < 16; h++) vf[16+h] = mean*temp_w[h] + stdv*temp_w[16+h] + temp_b[h];

    float ip = imp_b[0];
#pragma unroll
    for (int j = 0; j < 32; j++) ip += vf[j]*imp_w[j];
    g_imp[idx] = 1.f/(1.f + expf(-ip));

#pragma unroll
    for (int h = 0; h < 16; h++) {
        float qa = q_b[h], ka = k_b[h];
#pragma unroll
        for (int j = 0; j < 32; j++) { qa += vf[j]*q_w[j*16+h]; ka += vf[j]*k_w[j*16+h]; }
        g_Q[(size_t)idx*16 + h] = qa;
        g_K[(size_t)idx*16 + h] = ka;
    }
}

// ===================== sparse attention softmax =====================
__global__ void k_attn() {
    int w = threadIdx.x >> 5, lane = threadIdx.x & 31;
    int id = blockIdx.x*8 + w;
    int n = id & 511;
    int b = id >> 9;
    float qv[16];
#pragma unroll
    for (int h = 0; h < 16; h++) qv[h] = g_Q[(size_t)id*16 + h];
    int m1 = g_topk[n*TKV + lane];
    float s1 = 0.f;
#pragma unroll
    for (int h = 0; h < 16; h++) s1 += qv[h]*g_K[((size_t)b*512+m1)*16 + h];
    s1 *= 0.25f;
    float s2 = -3.0e38f;
    if (lane < TKV-32) {
        int m2 = g_topk[n*TKV + 32 + lane];
        float t = 0.f;
#pragma unroll
        for (int h = 0; h < 16; h++) t += qv[h]*g_K[((size_t)b*512+m2)*16 + h];
        s2 = t * 0.25f;
    }
    float mx = fmaxf(s1, s2);
#pragma unroll
    for (int o = 16; o; o >>= 1) mx = fmaxf(mx, __shfl_xor_sync(0xffffffffu, mx, o));
    float e1 = expf(s1 - mx);
    float e2 = (lane < TKV-32) ? expf(s2 - mx) : 0.f;
    float sm = e1 + e2;
#pragma unroll
    for (int o = 16; o; o >>= 1) sm += __shfl_xor_sync(0xffffffffu, sm, o);
    float inv = 1.f/sm;
    g_attn[(size_t)id*TKV + lane] = e1*inv;
    if (lane < TKV-32) g_attn[(size_t)id*TKV + 32 + lane] = e2*inv;
}

// ============ ring gather + mix -> A1 interleaved bf16 (float4 LDS) =========
__global__ void __launch_bounds__(512) k_ring(const float* __restrict__ x) {
    __shared__ __align__(16) float xs[512*20];
    int b = blockIdx.y, l0 = blockIdx.x*16;
    const float* xp = x + ((size_t)b*LL + l0)*NNV;
    for (int i = threadIdx.x; i < 16*512; i += 512) {
        int l = i >> 9, n = i & 511;
        xs[n*20 + l] = xp[(size_t)l*NNV + n];
    }
    __syncthreads();
    int n = threadIdx.x;
    float acc[16];
#pragma unroll
    for (int l = 0; l < 16; l++) acc[l] = 0.f;
    size_t abase = ((size_t)b*512 + n)*TKV;
    int ibase = n*TKV;
    const float4* xs4 = (const float4*)xs;
    for (int k = 0; k < TKV; k++) {
        float a = g_attn[abase + k];
        int m = g_topk[ibase + k];
        const float4* xm = xs4 + m*5;
        float4 v0 = xm[0], v1 = xm[1], v2 = xm[2], v3 = xm[3];
        acc[0]  += a*v0.x; acc[1]  += a*v0.y; acc[2]  += a*v0.z; acc[3]  += a*v0.w;
        acc[4]  += a*v1.x; acc[5]  += a*v1.y; acc[6]  += a*v1.z; acc[7]  += a*v1.w;
        acc[8]  += a*v2.x; acc[9]  += a*v2.y; acc[10] += a*v2.z; acc[11] += a*v2.w;
        acc[12] += a*v3.x; acc[13] += a*v3.y; acc[14] += a*v3.z; acc[15] += a*v3.w;
    }
    float imp = g_imp[b*512 + n];
    float omi = 1.f - imp;
    const float* xn = xs + n*20;
    size_t cbase = (size_t)((n>>5)*64 + (n&31));
#pragma unroll
    for (int l = 0; l < 16; l++) {
        size_t row = (size_t)b*LL + l0 + l;
        float v = imp*acc[l] + omi*xn[l];
        __nv_bfloat16 h, lo;
        bfsplit(v, h, lo);
        size_t o = row*KI + cbase;
        g_A1[o] = h;
        g_A1[o+32] = lo;
    }
}

// ===================== cluster weights =====================
__global__ void k_cw(const float* __restrict__ cluster_score) {
    int n = blockIdx.x*256 + threadIdx.x;
    if (n >= NNV) return;
    float v[16], mx = -3e38f;
#pragma unroll
    for (int c = 0; c < 16; c++) { v[c] = cluster_score[n*16+c]; mx = fmaxf(mx, v[c]); }
    float s = 0.f;
#pragma unroll
    for (int c = 0; c < 16; c++) { v[c] = expf(v[c]-mx); s += v[c]; }
    float inv = 1.f/s;
#pragma unroll
    for (int c = 0; c < 16; c++) {
        float e = v[c]*inv;
        g_cw[n*16+c] = e;
        g_cwT[c*512+n] = e;
    }
}

__global__ void k_prep(const float* __restrict__ varproj_w, const float* __restrict__ varproj_b,
                       const float* __restrict__ cp1_w, const float* __restrict__ cp1_b,
                       const float* __restrict__ cp2_w, const float* __restrict__ cp2_b) {
    int tid = threadIdx.x;
    for (int id = tid; id < 1024; id += 256) {
        int c = id >> 6, e = id & 63;
        float s = 0.f;
        for (int d = 0; d < 64; d++) s += varproj_w[c*64+d]*cp1_w[d*64+e];
        g_M1[id] = s;
    }
    if (tid < 64) {
        int e = tid;
        float bbv = cp1_b[e];
        for (int d = 0; d < 64; d++) bbv += varproj_b[d]*cp1_w[d*64+e];
        g_bb[e] = bbv;
        float w2 = 0.f;
        for (int d = 0; d < 64; d++) w2 += cp2_w[e*64+d];
        g_w2[e] = w2;
    }
    if (tid == 0) {
        float s = 0.f;
        for (int d = 0; d < 64; d++) s += cp2_b[d];
        g_b2s = s;
    }
}

// ===== weight transpose + bf16 split + rank-16 fold, interleaved (R8) =====
__global__ void k_prepw(const float* __restrict__ Wd, const float* __restrict__ Wr,
                        __nv_bfloat16* __restrict__ o) {
    __shared__ float colv[512];
    int n = blockIdx.x;
    int tid = threadIdx.x;   // 128
    for (int k = tid; k < 512; k += 128) {
        float w = Wd[(size_t)k*512 + n];
        __nv_bfloat16 h, l;
        bfsplit(w, h, l);
        size_t io = (size_t)n*KI + (size_t)((k>>5)*64 + (k&31));
        o[io] = h;
        o[io+32] = l;
    }
    for (int m = tid; m < 512; m += 128) colv[m] = Wr[(size_t)m*512 + n];
    __syncthreads();
    if (tid < 16) {
        float s = 0.f;
        for (int m = 0; m < 512; m++) s += g_cwT[tid*512 + m]*colv[m];
        __nv_bfloat16 h, l;
        bfsplit(s, h, l);
        size_t io = (size_t)n*KI + 1024 + tid;
        o[io] = h;
        o[io+32] = l;
    } else if (tid < 32) {
        __nv_bfloat16 z = __float2bfloat16(0.f);
        size_t io = (size_t)n*KI + 1024 + tid;
        o[io] = z;
        o[io+32] = z;
    }
}

// ===================== center tokens + projection =====================
__global__ void k_ct(const float* __restrict__ cg_w, const float* __restrict__ cg_b) {
    int b = blockIdx.x;
    int j = blockIdx.y*256 + threadIdx.x;
    float s = cg_b[j];
    for (int n = 0; n < NNV; n++) s += g_summary[b*512+n]*cg_w[(size_t)n*1024 + j];
    g_ct[b*1024 + j] = s;
}

__global__ void k_ctp(const float* __restrict__ cp1_w) {
    int id = blockIdx.x*256 + threadIdx.x;
    if (id >= BB*16*64) return;
    int b = id >> 10;
    int cd = id & 1023;
    int c = cd >> 6, e = cd & 63;
    float s = 0.f;
    for (int d = 0; d < 64; d++) s += g_ct[b*1024 + c*64 + d]*cp1_w[d*64+e];
    g_ctp[id] = s;
}

// ===================== xcs = x @ cw =====================
__global__ void k_xcs(const float* __restrict__ x) {
    __shared__ float xs[16*512];
    int row0 = blockIdx.x*16;
    const float* xp = x + (size_t)row0*NNV;
    for (int i = threadIdx.x; i < 16*512; i += 256) xs[i] = xp[i];
    __syncthreads();
    int l = threadIdx.x >> 4, c = threadIdx.x & 15;
    float s = 0.f;
    for (int n = 0; n < NNV; n++) s += xs[l*512+n]*__ldg(&g_cw[n*16+c]);
    g_xcs[(size_t)(row0+l)*16 + c] = s;
}

// ========== Sc (gelu-folded) + c2v + Sc K-extension (interleaved) ==========
__global__ void k_scc2v() {
    __shared__ float sxc[16], sx[64], red[128], sSc[16];
    size_t bl = blockIdx.x;
    int b = (int)(bl >> 11);
    int tid = threadIdx.x;
    if (tid < 16) sxc[tid] = g_xcs[bl*16 + tid];
    __syncthreads();
    if (tid < 64) {
        float s = g_bb[tid];
#pragma unroll
        for (int c = 0; c < 16; c++) s += sxc[c]*g_M1[c*64 + tid];
        sx[tid] = s;
    }
    __syncthreads();
    int c = tid >> 3, gi = tid & 7;
    float p = 0.f;
    const float* ctp = &g_ctp[(size_t)b*1024 + c*64];
#pragma unroll
    for (int ee = 0; ee < 8; ee++) {
        int e = gi*8 + ee;
        float t = sx[e] + ctp[e];
        p += (0.5f*t*(1.f + erff(t*0.70710678118654752f)))*g_w2[e];
    }
    red[tid] = p;
    __syncthreads();
    if (tid < 16) {
        float s = g_b2s;
#pragma unroll
        for (int gg = 0; gg < 8; gg++) s += red[tid*8 + gg];
        sSc[tid] = s;
    }
    __syncthreads();
    if (tid < 16) {
        float v = sSc[tid];
        __nv_bfloat16 h, l;
        bfsplit(v, h, l);
        size_t o = bl*KI + 1024 + tid;
        g_A1[o] = h; g_A1[o+32] = l;
        g_A2[o] = h; g_A2[o+32] = l;
    } else if (tid < 32) {
        __nv_bfloat16 z = __float2bfloat16(0.f);
        size_t o = bl*KI + 1024 + tid;
        g_A1[o] = z; g_A1[o+32] = z;
        g_A2[o] = z; g_A2[o+32] = z;
    }
    float sc[16];
#pragma unroll
    for (int cc = 0; cc < 16; cc++) sc[cc] = sSc[cc];
    float* op = &g_c2v[bl*NNV];
    for (int n = tid; n < NNV; n += 128) {
        float a = 0.f;
#pragma unroll
        for (int cc = 0; cc < 16; cc++) a += sc[cc]*__ldg(&g_cwT[cc*512 + n]);
        op[n] = a;
    }
}

// ========== launch (3 created streams + default main chain) =====
extern "C" void kernel_launch(void* const* d_in, const int* in_sizes, int n_in,
                              void* d_out, int out_size) {
    const float* x          = (const float*)d_in[0];
    const float* var_embed  = (const float*)d_in[1];
    const float* temp_w     = (const float*)d_in[2];
    const float* temp_b     = (const float*)d_in[3];
    const float* q_w        = (const float*)d_in[4];
    const float* q_b        = (const float*)d_in[5];
    const float* k_w        = (const float*)d_in[6];
    const float* k_b        = (const float*)d_in[7];
    const float* imp_w      = (const float*)d_in[8];
    const float* imp_b      = (const float*)d_in[9];
    const float* cluster_sc = (const float*)d_in[10];
    const float* varproj_w  = (const float*)d_in[11];
    const float* varproj_b  = (const float*)d_in[12];
    const float* cp1_w      = (const float*)d_in[13];
    const float* cp1_b      = (const float*)d_in[14];
    const float* cp2_w      = (const float*)d_in[15];
    const float* cp2_b      = (const float*)d_in[16];
    const float* cg_w       = (const float*)d_in[17];
    const float* cg_b       = (const float*)d_in[18];
    const float* gate_w     = (const float*)d_in[19];
    const float* gate_b     = (const float*)d_in[20];
    const float* fus_w      = (const float*)d_in[21];
    const float* fus_b      = (const float*)d_in[22];
    const float* ln_g       = (const float*)d_in[23];
    const float* ln_b       = (const float*)d_in[24];
    float* out = (float*)d_out;

    float *p_c2v, *p_h, *p_simpart;
    __nv_bfloat16 *pA1, *pA2, *pB1, *pB2, *pnT;
    cudaGetSymbolAddress((void**)&p_c2v,  g_c2v);
    cudaGetSymbolAddress((void**)&p_h,    g_h);
    cudaGetSymbolAddress((void**)&p_simpart, g_simpart);
    cudaGetSymbolAddress((void**)&pA1, g_A1);
    cudaGetSymbolAddress((void**)&pA2, g_A2);
    cudaGetSymbolAddress((void**)&pB1, g_B1);
    cudaGetSymbolAddress((void**)&pB2, g_B2);
    cudaGetSymbolAddress((void**)&pnT, g_nT);

    const int GSMEM = 3 * STAGEB;   // 98304 bytes
    cudaFuncSetAttribute(k_gsim, cudaFuncAttributeMaxDynamicSharedMemorySize, GSMEM);
    cudaFuncSetAttribute(k_gf,   cudaFuncAttributeMaxDynamicSharedMemorySize, FSMEM);

    static cudaStream_t sA = nullptr, sB = nullptr, sC = nullptr;
    static cudaEvent_t evRoot, evTopk, evRouter, evCw, evSB, evSC;
    if (sA == nullptr) {
        cudaStreamCreateWithFlags(&sA, cudaStreamNonBlocking);
        cudaStreamCreateWithFlags(&sB, cudaStreamNonBlocking);
        cudaStreamCreateWithFlags(&sC, cudaStreamNonBlocking);
        cudaEventCreateWithFlags(&evRoot,   cudaEventDisableTiming);
        cudaEventCreateWithFlags(&evTopk,   cudaEventDisableTiming);
        cudaEventCreateWithFlags(&evRouter, cudaEventDisableTiming);
        cudaEventCreateWithFlags(&evCw,     cudaEventDisableTiming);
        cudaEventCreateWithFlags(&evSB,     cudaEventDisableTiming);
        cudaEventCreateWithFlags(&evSC,     cudaEventDisableTiming);
    }

    cudaEventRecord(evRoot, 0);

    // ---- stream A: mask path (critical) ----
    cudaStreamWaitEvent(sA, evRoot, 0);
    k_colstats<<<dim3(LL/64, NNV/64), 256, 0, sA>>>(x);
    k_gsim<<<dim3(4,4,SIMZ), 256, GSMEM, sA>>>(pnT, NTI, (LL/SIMZ)/32, (LL/SIMZ)/32,
                                               p_simpart);
    k_simred<<<NNV*NNV/256, 256, 0, sA>>>();
    k_topk<<<NNV/4, 128, 0, sA>>>();
    cudaEventRecord(evTopk, sA);

    // ---- stream C: cluster weights + weight prep ----
    cudaStreamWaitEvent(sC, evRoot, 0);
    k_cw<<<2, 256, 0, sC>>>(cluster_sc);
    k_prep<<<1, 256, 0, sC>>>(varproj_w, varproj_b, cp1_w, cp1_b, cp2_w, cp2_b);
    cudaEventRecord(evCw, sC);
    k_prepw<<<512, 128, 0, sC>>>(gate_w, gate_w + 512*512, pB1);
    k_prepw<<<512, 128, 0, sC>>>(fus_w, fus_w, pB2);
    cudaEventRecord(evSC, sC);

    // ---- stream B: router stats + center path ----
    cudaStreamWaitEvent(sB, evRoot, 0);
    k_partsums<<<BB*16, 256, 0, sB>>>(x);
    k_router<<<BB*NNV/256, 256, 0, sB>>>(var_embed, temp_w, temp_b, q_w, q_b, k_w, k_b, imp_w, imp_b);
    cudaEventRecord(evRouter, sB);
    cudaStreamWaitEvent(sB, evCw, 0);
    k_ct<<<dim3(BB, 4), 256, 0, sB>>>(cg_w, cg_b);
    k_ctp<<<BB*16*64/256, 256, 0, sB>>>(cp1_w);
    k_xcs<<<BLV/16, 256, 0, sB>>>(x);
    k_scc2v<<<BLV, 128, 0, sB>>>();
    cudaEventRecord(evSB, sB);

    // ---- default stream: attention -> ring -> fused GEMMs+LN ----
    cudaStreamWaitEvent(0, evTopk, 0);
    cudaStreamWaitEvent(0, evRouter, 0);
    k_attn<<<BB*NNV/8, 256>>>();
    k_ring<<<dim3(LL/16, BB), 512>>>(x);
    cudaStreamWaitEvent(0, evSB, 0);
    cudaStreamWaitEvent(0, evSC, 0);
    k_gf<<<BLV/64, 256, FSMEM>>>(pA1, pA2, pB1, pB2, gate_b, fus_b, p_c2v, x, p_h,
                                 ln_g, ln_b, out);

    (void)in_sizes; (void)n_in; (void)out_size;
}